// round 1
// baseline (speedup 1.0000x reference)
#include <cuda_runtime.h>
#include <math.h>

#define BB 8
#define HH 1024
#define DD 4
#define TI 32
#define TJ 32

// Scratch: precomputed trig tables (static __device__ arrays — no runtime alloc)
__device__ float g_ca[HH * HH];          // cos(alpha[i,j])
__device__ float g_sa[HH * HH];          // sin(alpha[i,j])
__device__ float g_sth[BB * HH * DD];    // sin(theta[b,h,d])
__device__ float g_cth[BB * HH * DD];    // cos(theta[b,h,d])

// ---------------------------------------------------------------------------
// Kernel 1: trig precompute. idx < H*H -> alpha tables; else theta tables.
// ---------------------------------------------------------------------------
__global__ void vk_trig_kernel(const float* __restrict__ alpha,
                               const float* __restrict__ theta) {
    int idx = blockIdx.x * blockDim.x + threadIdx.x;
    const int NA = HH * HH;
    const int NT = BB * HH * DD;
    if (idx < NA) {
        float s, c;
        sincosf(alpha[idx], &s, &c);
        g_sa[idx] = s;
        g_ca[idx] = c;
    } else if (idx < NA + NT) {
        int t = idx - NA;
        float s, c;
        sincosf(theta[t], &s, &c);
        g_sth[t] = s;
        g_cth[t] = c;
    }
}

// ---------------------------------------------------------------------------
// Kernel 2: main coupling kernel.
// Grid: (H/TI, B). Block: 1024 threads = 32 warps. Warp w owns row i = i0+w.
// Lanes stride over j in tiles of 32. The A-transpose read (A[b,j,i]) is
// staged through a padded shared tile so both global reads are coalesced.
//
//   a    = relu(0.5*(A[b,i,j] + A[b,j,i]))
//   w1   = a*cos(alpha[i,j]);  w2 = a*sin(alpha[i,j])
//   S1_d = sum_j (w1*sj_d - w2*cj_d)
//   S2_d = sum_j (w1*cj_d + w2*sj_d)
//   coupling_d = (1/H) * (ci_d*S1_d - si_d*S2_d)
// ---------------------------------------------------------------------------
__global__ __launch_bounds__(1024, 2)
void vk_main_kernel(const float* __restrict__ theta,
                    const float* __restrict__ gamma,
                    const float* __restrict__ A,
                    const float* __restrict__ omega,
                    const float* __restrict__ kappa,
                    float* __restrict__ out) {
    const int b  = blockIdx.y;
    const int i0 = blockIdx.x * TI;
    const int warp = threadIdx.x >> 5;
    const int lane = threadIdx.x & 31;
    const int i = i0 + warp;

    __shared__ float shAt[TJ][TI + 1];   // A[b, j0+jj, i0+ii], padded
    __shared__ float4 shS[TJ];           // sin(theta[b, j0+jj, 0..3])
    __shared__ float4 shC[TJ];           // cos(theta[b, j0+jj, 0..3])

    float s1x = 0.f, s1y = 0.f, s1z = 0.f, s1w = 0.f;
    float s2x = 0.f, s2y = 0.f, s2z = 0.f, s2w = 0.f;

    const float* Ab = A + (size_t)b * HH * HH;
    const float* Arow = Ab + (size_t)i * HH;          // A[b,i,:]
    const float* carow = g_ca + (size_t)i * HH;
    const float* sarow = g_sa + (size_t)i * HH;
    const float4* sth4 = (const float4*)(g_sth + (size_t)b * HH * DD);
    const float4* cth4 = (const float4*)(g_cth + (size_t)b * HH * DD);

    for (int j0 = 0; j0 < HH; j0 += TJ) {
        __syncthreads();
        // Cooperative load of transpose tile: tid -> (jj = tid>>5, ii = tid&31)
        {
            int jj = warp;          // reuse decomposition: tid>>5
            int ii = lane;
            shAt[jj][ii] = Ab[(size_t)(j0 + jj) * HH + (i0 + ii)];
        }
        // Stage sin/cos theta for this j-tile (first 32 threads each)
        if (threadIdx.x < TJ) {
            shS[threadIdx.x] = sth4[j0 + threadIdx.x];
        } else if (threadIdx.x >= 32 && threadIdx.x < 32 + TJ) {
            shC[threadIdx.x - 32] = cth4[j0 + threadIdx.x - 32];
        }
        __syncthreads();

        const int j = j0 + lane;
        float arow = Arow[j];                 // coalesced across lanes
        float at   = shAt[lane][warp];        // stride-33 -> conflict-free
        float a    = 0.5f * (arow + at);
        a = fmaxf(a, 0.f);
        float ca = carow[j];                  // coalesced
        float sa = sarow[j];                  // coalesced
        float w1 = a * ca;
        float w2 = a * sa;

        float4 s = shS[lane];
        float4 c = shC[lane];

        s1x = fmaf(w1, s.x, s1x); s1x = fmaf(-w2, c.x, s1x);
        s1y = fmaf(w1, s.y, s1y); s1y = fmaf(-w2, c.y, s1y);
        s1z = fmaf(w1, s.z, s1z); s1z = fmaf(-w2, c.z, s1z);
        s1w = fmaf(w1, s.w, s1w); s1w = fmaf(-w2, c.w, s1w);

        s2x = fmaf(w1, c.x, s2x); s2x = fmaf(w2, s.x, s2x);
        s2y = fmaf(w1, c.y, s2y); s2y = fmaf(w2, s.y, s2y);
        s2z = fmaf(w1, c.z, s2z); s2z = fmaf(w2, s.z, s2z);
        s2w = fmaf(w1, c.w, s2w); s2w = fmaf(w2, s.w, s2w);
    }

    // Warp butterfly reduction of 8 accumulators
    #pragma unroll
    for (int off = 16; off > 0; off >>= 1) {
        s1x += __shfl_xor_sync(0xFFFFFFFFu, s1x, off);
        s1y += __shfl_xor_sync(0xFFFFFFFFu, s1y, off);
        s1z += __shfl_xor_sync(0xFFFFFFFFu, s1z, off);
        s1w += __shfl_xor_sync(0xFFFFFFFFu, s1w, off);
        s2x += __shfl_xor_sync(0xFFFFFFFFu, s2x, off);
        s2y += __shfl_xor_sync(0xFFFFFFFFu, s2y, off);
        s2z += __shfl_xor_sync(0xFFFFFFFFu, s2z, off);
        s2w += __shfl_xor_sync(0xFFFFFFFFu, s2w, off);
    }

    if (lane == 0) {
        const float invH = 1.0f / (float)HH;   // K_COUP = 1
        const size_t base = ((size_t)b * HH + i) * DD;
        float4 si4 = *(const float4*)(g_sth + base);
        float4 ci4 = *(const float4*)(g_cth + base);
        float4 tp4 = *(const float4*)(theta + base);
        float4 om4 = *(const float4*)(omega + (size_t)i * DD);
        float4 kp4 = *(const float4*)(kappa + (size_t)i * DD);
        float g = gamma[(size_t)b * HH + i];

        float4 r;
        // out = tp + DT*(omega + coupling + kappa*(gamma - tp)),  DT = 1
        r.x = tp4.x + om4.x + invH * (ci4.x * s1x - si4.x * s2x) + kp4.x * (g - tp4.x);
        r.y = tp4.y + om4.y + invH * (ci4.y * s1y - si4.y * s2y) + kp4.y * (g - tp4.y);
        r.z = tp4.z + om4.z + invH * (ci4.z * s1z - si4.z * s2z) + kp4.z * (g - tp4.z);
        r.w = tp4.w + om4.w + invH * (ci4.w * s1w - si4.w * s2w) + kp4.w * (g - tp4.w);
        *(float4*)(out + base) = r;
    }
}

extern "C" void kernel_launch(void* const* d_in, const int* in_sizes, int n_in,
                              void* d_out, int out_size) {
    const float* theta = (const float*)d_in[0];  // [B,H,D]
    const float* gamma = (const float*)d_in[1];  // [B,H]
    const float* A     = (const float*)d_in[2];  // [B,H,H]
    const float* omega = (const float*)d_in[3];  // [H,D]
    const float* kappa = (const float*)d_in[4];  // [H,D]
    const float* alpha = (const float*)d_in[5];  // [H,H]
    float* out = (float*)d_out;

    // Kernel 1: trig tables
    {
        int n = HH * HH + BB * HH * DD;
        int threads = 256;
        int blocks = (n + threads - 1) / threads;
        vk_trig_kernel<<<blocks, threads>>>(alpha, theta);
    }
    // Kernel 2: main
    {
        dim3 grid(HH / TI, BB);
        vk_main_kernel<<<grid, 1024>>>(theta, gamma, A, omega, kappa, out);
    }
}

// round 2
// speedup vs baseline: 1.5401x; 1.5401x over previous
#include <cuda_runtime.h>
#include <math.h>

#define BB 8
#define HH 1024
#define DD 4
#define TI 16          // output rows per block
#define TJ 128         // j-tile width
#define NW 8           // warps per block (256 threads)
#define RPW 2          // rows per warp
#define PADS 132       // shared tile row stride (multiple of 4, low-conflict)

// Scratch: precomputed trig tables (__device__ globals: allocation-guard safe)
__device__ float g_ca[HH * HH];        // 0.5*cos(alpha[i,j])
__device__ float g_sa[HH * HH];        // 0.5*sin(alpha[i,j])
__device__ float g_sth[BB * HH * DD];  // sin(theta)
__device__ float g_cth[BB * HH * DD];  // cos(theta)

typedef unsigned long long u64;

__device__ __forceinline__ u64 pack2(float x, float y) {
    u64 r; asm("mov.b64 %0, {%1, %2};" : "=l"(r) : "f"(x), "f"(y)); return r;
}
__device__ __forceinline__ u64 ffma2(u64 a, u64 b, u64 c) {
    u64 d; asm("fma.rn.f32x2 %0, %1, %2, %3;" : "=l"(d) : "l"(a), "l"(b), "l"(c)); return d;
}
__device__ __forceinline__ float2 unpk2(u64 v) {
    float x, y; asm("mov.b64 {%0, %1}, %2;" : "=f"(x), "=f"(y) : "l"(v));
    return make_float2(x, y);
}

// ---------------------------------------------------------------------------
// Kernel 1: trig precompute. 0.5 factor folded into alpha tables.
// ---------------------------------------------------------------------------
__global__ void vk_trig_kernel(const float* __restrict__ alpha,
                               const float* __restrict__ theta) {
    int idx = blockIdx.x * blockDim.x + threadIdx.x;
    const int NA = HH * HH;
    const int NT = BB * HH * DD;
    if (idx < NA) {
        float s, c;
        sincosf(alpha[idx], &s, &c);
        g_sa[idx] = 0.5f * s;
        g_ca[idx] = 0.5f * c;
    } else if (idx < NA + NT) {
        int t = idx - NA;
        float s, c;
        sincosf(theta[t], &s, &c);
        g_sth[t] = s;
        g_cth[t] = c;
    }
}

// One (i,j) pair update: a = relu(arow+at); w1 = a*ca', w2 = a*sa'
// s1 += w1*sj - w2*cj ; s2 += w1*cj + w2*sj  (packed over d-pairs)
#define KSTEP(av, tv, cav, sav, SS, CC, A0, A1, A2, A3)        \
    {                                                          \
        float m_  = fmaxf((av) + (tv), 0.f);                   \
        float w1_ = m_ * (cav);                                \
        float w2_ = m_ * (sav);                                \
        u64 w1p_  = pack2(w1_, w1_);                           \
        u64 w2p_  = pack2(w2_, w2_);                           \
        u64 nw2p_ = pack2(-w2_, -w2_);                         \
        A0 = ffma2(w1p_, (SS).x, A0); A0 = ffma2(nw2p_, (CC).x, A0); \
        A1 = ffma2(w1p_, (SS).y, A1); A1 = ffma2(nw2p_, (CC).y, A1); \
        A2 = ffma2(w1p_, (CC).x, A2); A2 = ffma2(w2p_, (SS).x, A2);  \
        A3 = ffma2(w1p_, (CC).y, A3); A3 = ffma2(w2p_, (SS).y, A3);  \
    }

// Process one row r against the lane's 4 j's
#define ROWSTEP(iG, ROWIDX, A0, A1, A2, A3)                                   \
    {                                                                         \
        const size_t ro_ = (size_t)(iG) * HH + j;                             \
        float4 ar_ = *(const float4*)(Ab + ro_);                              \
        float4 at_ = *(const float4*)(shAt + (ROWIDX) * PADS + lane * 4);     \
        float4 ca_ = *(const float4*)(g_ca + ro_);                            \
        float4 sa_ = *(const float4*)(g_sa + ro_);                            \
        KSTEP(ar_.x, at_.x, ca_.x, sa_.x, s0, c0, A0, A1, A2, A3);            \
        KSTEP(ar_.y, at_.y, ca_.y, sa_.y, s1, c1, A0, A1, A2, A3);            \
        KSTEP(ar_.z, at_.z, ca_.z, sa_.z, s2, c2, A0, A1, A2, A3);            \
        KSTEP(ar_.w, at_.w, ca_.w, sa_.w, s3, c3, A0, A1, A2, A3);            \
    }

// ---------------------------------------------------------------------------
// Kernel 2: main coupling. Grid (H/TI, B), block 256 = 8 warps.
// Warp w owns rows i0 + 2w, i0 + 2w + 1. Lane owns 4 consecutive j's/tile.
// A^T tile staged in shared (row-major [ii][jj], stride PADS) for coalescing.
// ---------------------------------------------------------------------------
__global__ __launch_bounds__(256)
void vk_main_kernel(const float* __restrict__ theta,
                    const float* __restrict__ gamma,
                    const float* __restrict__ A,
                    const float* __restrict__ omega,
                    const float* __restrict__ kappa,
                    float* __restrict__ out) {
    const int b    = blockIdx.y;
    const int i0   = blockIdx.x * TI;
    const int tid  = threadIdx.x;
    const int warp = tid >> 5;
    const int lane = tid & 31;

    __shared__ float shAt[TI * PADS];  // shAt[ii*PADS + jj] = A[b, j0+jj, i0+ii]

    const float* Ab = A + (size_t)b * HH * HH;
    const ulonglong2* sv = (const ulonglong2*)(g_sth + (size_t)b * HH * DD);
    const ulonglong2* cv = (const ulonglong2*)(g_cth + (size_t)b * HH * DD);

    const int iA = i0 + warp * RPW;       // row 0 of this warp
    const int iB = iA + 1;                // row 1

    u64 A00 = 0, A01 = 0, A02 = 0, A03 = 0;   // row A: s1(d01), s1(d23), s2(d01), s2(d23)
    u64 A10 = 0, A11 = 0, A12 = 0, A13 = 0;   // row B

    const int ldr_ii = tid & 15;
    const int ldr_jj = tid >> 4;

    for (int j0 = 0; j0 < HH; j0 += TJ) {
        __syncthreads();
        // Cooperative transpose-tile load: 128x16 elems, 8 per thread
        #pragma unroll
        for (int p = 0; p < 8; p++) {
            int jj = ldr_jj + p * 16;
            shAt[ldr_ii * PADS + jj] =
                Ab[(size_t)(j0 + jj) * HH + (i0 + ldr_ii)];
        }
        __syncthreads();

        const int j = j0 + lane * 4;
        // theta trig for the lane's 4 j's (64B contiguous per lane)
        ulonglong2 s0 = sv[j],     c0 = cv[j];
        ulonglong2 s1 = sv[j + 1], c1 = cv[j + 1];
        ulonglong2 s2 = sv[j + 2], c2 = cv[j + 2];
        ulonglong2 s3 = sv[j + 3], c3 = cv[j + 3];

        ROWSTEP(iA, warp * RPW + 0, A00, A01, A02, A03);
        ROWSTEP(iB, warp * RPW + 1, A10, A11, A12, A13);
    }

    // Unpack 8 packed accumulators -> 16 floats, warp butterfly reduce
    float v[16];
    {
        float2 t;
        t = unpk2(A00); v[0]  = t.x; v[1]  = t.y;
        t = unpk2(A01); v[2]  = t.x; v[3]  = t.y;
        t = unpk2(A02); v[4]  = t.x; v[5]  = t.y;
        t = unpk2(A03); v[6]  = t.x; v[7]  = t.y;
        t = unpk2(A10); v[8]  = t.x; v[9]  = t.y;
        t = unpk2(A11); v[10] = t.x; v[11] = t.y;
        t = unpk2(A12); v[12] = t.x; v[13] = t.y;
        t = unpk2(A13); v[14] = t.x; v[15] = t.y;
    }
    #pragma unroll
    for (int off = 16; off > 0; off >>= 1) {
        #pragma unroll
        for (int q = 0; q < 16; q++)
            v[q] += __shfl_xor_sync(0xFFFFFFFFu, v[q], off);
    }

    if (lane < RPW) {
        const int r = lane;
        const int i = iA + r;
        const float* vv = v + r * 8;   // [s1_d0,s1_d1,s1_d2,s1_d3, s2_d0..d3]
        const float invH = 1.0f / (float)HH;  // K_COUP=1, 0.5 already folded
        const size_t base = ((size_t)b * HH + i) * DD;
        float4 si4 = *(const float4*)(g_sth + base);
        float4 ci4 = *(const float4*)(g_cth + base);
        float4 tp4 = *(const float4*)(theta + base);
        float4 om4 = *(const float4*)(omega + (size_t)i * DD);
        float4 kp4 = *(const float4*)(kappa + (size_t)i * DD);
        float g = gamma[(size_t)b * HH + i];

        float4 rr;
        rr.x = tp4.x + om4.x + invH * (ci4.x * vv[0] - si4.x * vv[4]) + kp4.x * (g - tp4.x);
        rr.y = tp4.y + om4.y + invH * (ci4.y * vv[1] - si4.y * vv[5]) + kp4.y * (g - tp4.y);
        rr.z = tp4.z + om4.z + invH * (ci4.z * vv[2] - si4.z * vv[6]) + kp4.z * (g - tp4.z);
        rr.w = tp4.w + om4.w + invH * (ci4.w * vv[3] - si4.w * vv[7]) + kp4.w * (g - tp4.w);
        *(float4*)(out + base) = rr;
    }
}

extern "C" void kernel_launch(void* const* d_in, const int* in_sizes, int n_in,
                              void* d_out, int out_size) {
    const float* theta = (const float*)d_in[0];  // [B,H,D]
    const float* gamma = (const float*)d_in[1];  // [B,H]
    const float* A     = (const float*)d_in[2];  // [B,H,H]
    const float* omega = (const float*)d_in[3];  // [H,D]
    const float* kappa = (const float*)d_in[4];  // [H,D]
    const float* alpha = (const float*)d_in[5];  // [H,H]
    float* out = (float*)d_out;

    {
        int n = HH * HH + BB * HH * DD;
        int threads = 256;
        int blocks = (n + threads - 1) / threads;
        vk_trig_kernel<<<blocks, threads>>>(alpha, theta);
    }
    {
        dim3 grid(HH / TI, BB);
        vk_main_kernel<<<grid, 256>>>(theta, gamma, A, omega, kappa, out);
    }
}

// round 4
// speedup vs baseline: 2.4268x; 1.5758x over previous
#include <cuda_runtime.h>
#include <math.h>
#include <stdint.h>

#define BB 8
#define HH 1024
#define DD 4
#define TI 16          // output rows per block
#define TJ 128         // j-tile width
#define PADI 17        // padded i-stride of transpose tile (odd -> conflict-free)
#define NBUF 3         // pipeline stages
#define NTILE (HH / TJ)

// Scratch (__device__ globals: allocation-guard safe)
__device__ float2 g_casa[HH * HH];     // (0.5*cos(alpha), 0.5*sin(alpha))
__device__ float  g_sth[BB * HH * DD]; // sin(theta)
__device__ float  g_cth[BB * HH * DD]; // cos(theta)

typedef unsigned long long u64;

__device__ __forceinline__ u64 pack2(float x, float y) {
    u64 r; asm("mov.b64 %0, {%1, %2};" : "=l"(r) : "f"(x), "f"(y)); return r;
}
__device__ __forceinline__ u64 ffma2(u64 a, u64 b, u64 c) {
    u64 d; asm("fma.rn.f32x2 %0, %1, %2, %3;" : "=l"(d) : "l"(a), "l"(b), "l"(c)); return d;
}
__device__ __forceinline__ float2 unpk2(u64 v) {
    float x, y; asm("mov.b64 {%0, %1}, %2;" : "=f"(x), "=f"(y) : "l"(v));
    return make_float2(x, y);
}
__device__ __forceinline__ void cp_async4(uint32_t s, const void* g) {
    asm volatile("cp.async.ca.shared.global [%0], [%1], 4;" :: "r"(s), "l"(g));
}
__device__ __forceinline__ void cp_async16(uint32_t s, const void* g) {
    asm volatile("cp.async.cg.shared.global [%0], [%1], 16;" :: "r"(s), "l"(g));
}
__device__ __forceinline__ void cp_commit() {
    asm volatile("cp.async.commit_group;");
}
__device__ __forceinline__ void cp_wait1() {
    asm volatile("cp.async.wait_group 1;");
}

// ---------------------------------------------------------------------------
// Kernel 1: trig precompute (0.5 of symmetrization folded into alpha tables)
// ---------------------------------------------------------------------------
__global__ void vk_trig_kernel(const float* __restrict__ alpha,
                               const float* __restrict__ theta) {
    int idx = blockIdx.x * blockDim.x + threadIdx.x;
    const int NA = HH * HH;
    const int NT = BB * HH * DD;
    if (idx < NA) {
        float s, c;
        sincosf(alpha[idx], &s, &c);
        g_casa[idx] = make_float2(0.5f * c, 0.5f * s);
    } else if (idx < NA + NT) {
        int t = idx - NA;
        float s, c;
        sincosf(theta[t], &s, &c);
        g_sth[t] = s;
        g_cth[t] = c;
    }
}

// One (i,j) pair: m = relu(ar+at); w1 = m*ca'; w2 = m*sa'
// s1 += w1*s - w2*c ; s2 += w1*c + w2*s   (packed f32x2 over d-pairs)
#define KPAIR(ar, at, cs, Sv, Cv, P0, P1, P2, P3)            \
    {                                                        \
        float m_  = fmaxf((ar) + (at), 0.f);                 \
        float w1_ = m_ * (cs).x;                             \
        float w2_ = m_ * (cs).y;                             \
        float n2_ = -w2_;                                    \
        u64 w1p_ = pack2(w1_, w1_);                          \
        u64 w2p_ = pack2(w2_, w2_);                          \
        u64 n2p_ = pack2(n2_, n2_);                          \
        P0 = ffma2(w1p_, (Sv).x, P0); P0 = ffma2(n2p_, (Cv).x, P0); \
        P1 = ffma2(w1p_, (Sv).y, P1); P1 = ffma2(n2p_, (Cv).y, P1); \
        P2 = ffma2(w1p_, (Cv).x, P2); P2 = ffma2(w2p_, (Sv).x, P2); \
        P3 = ffma2(w1p_, (Cv).y, P3); P3 = ffma2(w2p_, (Sv).y, P3); \
    }

// ---------------------------------------------------------------------------
// Kernel 2: main coupling. Grid (H/TI, B), block 256 = 8 warps, 2 rows/warp.
// 3-stage cp.async pipeline stages A-transpose tile + theta-trig tile in smem.
// Lane q-step covers j = j0 + 32q + lane (strided -> conflict-free LDS).
// ---------------------------------------------------------------------------
__global__ __launch_bounds__(256, 4)
void vk_main_kernel(const float* __restrict__ theta,
                    const float* __restrict__ gamma,
                    const float* __restrict__ A,
                    const float* __restrict__ omega,
                    const float* __restrict__ kappa,
                    float* __restrict__ out) {
    __shared__ float      shA[NBUF][TJ * PADI];  // [jj*PADI + ii] = A[b, j0+jj, i0+ii]
    __shared__ ulonglong2 shS[NBUF][TJ];         // sin(theta[b, j0+jj, 0..3])
    __shared__ ulonglong2 shC[NBUF][TJ];         // cos(theta[b, j0+jj, 0..3])

    const int b    = blockIdx.y;
    const int i0   = blockIdx.x * TI;
    const int tid  = threadIdx.x;
    const int warp = tid >> 5;
    const int lane = tid & 31;

    const float* Ab   = A + (size_t)b * HH * HH;
    const float* sthb = g_sth + (size_t)b * HH * DD;
    const float* cthb = g_cth + (size_t)b * HH * DD;

    const int riA = warp * 2;         // local row indices
    const int iA  = i0 + riA;
    const float*  ArowA = Ab + (size_t)iA * HH;
    const float*  ArowB = ArowA + HH;
    const float2* csA   = g_casa + (size_t)iA * HH;
    const float2* csB   = csA + HH;

    // staging thread mapping
    const int s_ii = tid & 15;
    const int s_jj = tid >> 4;

    // Stage tile tt into buffer s (one cp.async group per call)
    auto stage = [&](int tt, int sb) {
        const int j0_ = tt * TJ;
        uint32_t dA_ = (uint32_t)__cvta_generic_to_shared(&shA[sb][0]);
        #pragma unroll
        for (int p_ = 0; p_ < 8; p_++) {
            int jj_ = s_jj + p_ * 16;
            cp_async4(dA_ + (uint32_t)(jj_ * PADI + s_ii) * 4,
                      Ab + (size_t)(j0_ + jj_) * HH + (i0 + s_ii));
        }
        if (tid < 128) {
            cp_async16((uint32_t)__cvta_generic_to_shared(&shS[sb][tid]),
                       sthb + (size_t)(j0_ + tid) * DD);
        } else {
            cp_async16((uint32_t)__cvta_generic_to_shared(&shC[sb][tid - 128]),
                       cthb + (size_t)(j0_ + tid - 128) * DD);
        }
    };

    u64 A0 = 0, A1 = 0, A2 = 0, A3 = 0;  // row A: s1 d01, s1 d23, s2 d01, s2 d23
    u64 B0 = 0, B1 = 0, B2 = 0, B3 = 0;  // row B

    stage(0, 0); cp_commit();
    stage(1, 1); cp_commit();

    int s = 0;
    for (int t = 0; t < NTILE; t++) {
        cp_wait1();                 // tile t resident (t+1 may be in flight)
        __syncthreads();
        // issue tile t+2 into the buffer freed by tile t-1 (all warps are past it)
        int s2 = s + 2; if (s2 >= NBUF) s2 -= NBUF;
        if (t + 2 < NTILE) stage(t + 2, s2);
        cp_commit();                // always commit: keeps the group FIFO depth fixed

        const float*      bufA = shA[s];
        const ulonglong2* bufS = shS[s];
        const ulonglong2* bufC = shC[s];
        const int j0 = t * TJ;

        #pragma unroll
        for (int q = 0; q < 4; q++) {
            const int jl = q * 32 + lane;
            const int j  = j0 + jl;
            ulonglong2 Sv = bufS[jl];            // LDS.128, conflict-free
            ulonglong2 Cv = bufC[jl];
            float  atA = bufA[jl * PADI + riA];  // LDS.32, conflict-free (odd stride)
            float  atB = bufA[jl * PADI + riA + 1];
            float  arA = ArowA[j];               // coalesced LDG.32
            float  arB = ArowB[j];
            float2 caA = csA[j];                 // coalesced LDG.64
            float2 caB = csB[j];
            KPAIR(arA, atA, caA, Sv, Cv, A0, A1, A2, A3);
            KPAIR(arB, atB, caB, Sv, Cv, B0, B1, B2, B3);
        }
        s = s + 1; if (s >= NBUF) s = 0;
    }

    // Unpack + warp butterfly reduction (16 scalars)
    float v[16];
    {
        float2 t2;
        t2 = unpk2(A0); v[0]  = t2.x; v[1]  = t2.y;
        t2 = unpk2(A1); v[2]  = t2.x; v[3]  = t2.y;
        t2 = unpk2(A2); v[4]  = t2.x; v[5]  = t2.y;
        t2 = unpk2(A3); v[6]  = t2.x; v[7]  = t2.y;
        t2 = unpk2(B0); v[8]  = t2.x; v[9]  = t2.y;
        t2 = unpk2(B1); v[10] = t2.x; v[11] = t2.y;
        t2 = unpk2(B2); v[12] = t2.x; v[13] = t2.y;
        t2 = unpk2(B3); v[14] = t2.x; v[15] = t2.y;
    }
    #pragma unroll
    for (int off = 16; off > 0; off >>= 1) {
        #pragma unroll
        for (int qq = 0; qq < 16; qq++)
            v[qq] += __shfl_xor_sync(0xFFFFFFFFu, v[qq], off);
    }

    if (lane < 2) {
        const int i = iA + lane;
        const float* vv = v + lane * 8;       // [s1_d0..d3, s2_d0..d3]
        const float invH = 1.0f / (float)HH;  // K_COUP=1, DT=1, 0.5 folded
        const size_t base = ((size_t)b * HH + i) * DD;
        float4 si4 = *(const float4*)(g_sth + base);
        float4 ci4 = *(const float4*)(g_cth + base);
        float4 tp4 = *(const float4*)(theta + base);
        float4 om4 = *(const float4*)(omega + (size_t)i * DD);
        float4 kp4 = *(const float4*)(kappa + (size_t)i * DD);
        float g = gamma[(size_t)b * HH + i];

        float4 rr;
        rr.x = tp4.x + om4.x + invH * (ci4.x * vv[0] - si4.x * vv[4]) + kp4.x * (g - tp4.x);
        rr.y = tp4.y + om4.y + invH * (ci4.y * vv[1] - si4.y * vv[5]) + kp4.y * (g - tp4.y);
        rr.z = tp4.z + om4.z + invH * (ci4.z * vv[2] - si4.z * vv[6]) + kp4.z * (g - tp4.z);
        rr.w = tp4.w + om4.w + invH * (ci4.w * vv[3] - si4.w * vv[7]) + kp4.w * (g - tp4.w);
        *(float4*)(out + base) = rr;
    }
}

extern "C" void kernel_launch(void* const* d_in, const int* in_sizes, int n_in,
                              void* d_out, int out_size) {
    const float* theta = (const float*)d_in[0];  // [B,H,D]
    const float* gamma = (const float*)d_in[1];  // [B,H]
    const float* A     = (const float*)d_in[2];  // [B,H,H]
    const float* omega = (const float*)d_in[3];  // [H,D]
    const float* kappa = (const float*)d_in[4];  // [H,D]
    const float* alpha = (const float*)d_in[5];  // [H,H]
    float* out = (float*)d_out;

    {
        int n = HH * HH + BB * HH * DD;
        int threads = 256;
        int blocks = (n + threads - 1) / threads;
        vk_trig_kernel<<<blocks, threads>>>(alpha, theta);
    }
    {
        dim3 grid(HH / TI, BB);
        vk_main_kernel<<<grid, 256>>>(theta, gamma, A, omega, kappa, out);
    }
}